// round 10
// baseline (speedup 1.0000x reference)
#include <cuda_runtime.h>
#include <cuda_bf16.h>
#include <math.h>
#include <stdint.h>

// Problem dims
#define Bsz 512
#define Tsz 512
#define Lsz 64
#define Hsz 512
#define H3  1536                // 3*H
#define XW  (Tsz + Lsz - 1)     // 575

// ---------------- scratch (__device__ globals; no cudaMalloc) --------------
__device__ float g_GI1[(size_t)Lsz * Bsz * H3];  // [L*B][3H] fp32 (~201MB)
__device__ float g_GH1[Bsz * H3];
__device__ float g_GI2[Bsz * H3];
__device__ float g_GH2[Bsz * H3];
__device__ float g_H1[Bsz * Hsz];
__device__ float g_H2[Bsz * Hsz];

// split-bf16 planes (hi/lo); H1 planes ping-ponged by step parity
__device__ __align__(256) __nv_bfloat16 g_Whh1h[H3 * Hsz], g_Whh1l[H3 * Hsz];
__device__ __align__(256) __nv_bfloat16 g_Wih2h[H3 * Hsz], g_Wih2l[H3 * Hsz];
__device__ __align__(256) __nv_bfloat16 g_Whh2h[H3 * Hsz], g_Whh2l[H3 * Hsz];
__device__ __align__(256) __nv_bfloat16 g_Wih1h[H3 * Hsz], g_Wih1l[H3 * Hsz];
__device__ __align__(256) __nv_bfloat16 g_H1h[2 * Bsz * Hsz], g_H1l[2 * Bsz * Hsz];
__device__ __align__(256) __nv_bfloat16 g_H2h[Bsz * Hsz], g_H2l[Bsz * Hsz];
// windowed x, split planes: [L*B][512]
__device__ __align__(256) __nv_bfloat16 g_Axh[(size_t)Lsz * Bsz * Hsz];
__device__ __align__(256) __nv_bfloat16 g_Axl[(size_t)Lsz * Bsz * Hsz];

// ---------------- helpers ---------------------------------------------------
__device__ __forceinline__ uint32_t smem_u32(const void* p) {
    uint32_t a;
    asm("{ .reg .u64 t; cvta.to.shared.u64 t, %1; cvt.u32.u64 %0, t; }"
        : "=r"(a) : "l"(p));
    return a;
}
__device__ __forceinline__ void cp16(uint32_t dst, const void* src) {
    asm volatile("cp.async.cg.shared.global [%0], [%1], 16;" :: "r"(dst), "l"(src));
}
__device__ __forceinline__ void ldsm4(uint32_t& r0, uint32_t& r1, uint32_t& r2, uint32_t& r3,
                                      uint32_t addr) {
    asm volatile("ldmatrix.sync.aligned.m8n8.x4.shared.b16 {%0,%1,%2,%3}, [%4];"
                 : "=r"(r0), "=r"(r1), "=r"(r2), "=r"(r3) : "r"(addr));
}
__device__ __forceinline__ void mma16816(float* c, const uint32_t* a, const uint32_t* b) {
    asm volatile(
        "mma.sync.aligned.m16n8k16.row.col.f32.bf16.bf16.f32 "
        "{%0,%1,%2,%3}, {%4,%5,%6,%7}, {%8,%9}, {%0,%1,%2,%3};"
        : "+f"(c[0]), "+f"(c[1]), "+f"(c[2]), "+f"(c[3])
        : "r"(a[0]), "r"(a[1]), "r"(a[2]), "r"(a[3]), "r"(b[0]), "r"(b[1]));
}
__device__ __forceinline__ float sigmoidf_(float v) {
    return 1.f / (1.f + __expf(-v));
}
__device__ __forceinline__ void split_store(float v, __nv_bfloat16* hp, __nv_bfloat16* lp, size_t i) {
    __nv_bfloat16 h = __float2bfloat16(v);
    hp[i] = h;
    lp[i] = __float2bfloat16(v - __bfloat162float(h));
}

#define STAGES 3

// ---------------- split-bf16 GEMM core (mma.sync, 3-stage pipeline) ---------
// D[TM x 128] = sum_{K'=1536} A'(TM x K') * B'(128 x K')^T + bias
// segments of 512: 0:(Ah,Bh) 1:(Al,Bh) 2:(Ah,Bl); chunks of BK.
// TROW = BK*2 + 16 keeps ldmatrix conflict-free (TROW mod 128 in {80,16}).
template<int TM, int BK>
__device__ __forceinline__ void gemm_mma(
    const __nv_bfloat16* __restrict__ Ah, const __nv_bfloat16* __restrict__ Al, int m0,
    const __nv_bfloat16* __restrict__ Bh, const __nv_bfloat16* __restrict__ Bl, int n0,
    const float* __restrict__ bias, float* __restrict__ C, int ldc)
{
    extern __shared__ __align__(16) char smraw[];
    constexpr int TROW  = BK * 2 + 16;
    constexpr int ATILE = TM * TROW;
    constexpr int BTILE = 128 * TROW;
    constexpr int MA    = TM / 32;
    constexpr int NCH   = 1536 / BK;
    constexpr int CSEG  = 512 / BK;
    constexpr int Q     = BK / 8;
    constexpr int RPP   = 256 / Q;
    const uint32_t sA = smem_u32(smraw);
    const uint32_t sB = sA + STAGES * ATILE;

    const int tid  = threadIdx.x;
    const int wid  = tid >> 5;
    const int lane = tid & 31;
    const int wm0  = (wid & 1) * (TM / 2);
    const int wn0  = (wid >> 1) * 32;

    const int qrow = tid / Q;
    const int qk   = tid % Q;

    float acc[MA][4][4];
#pragma unroll
    for (int mi = 0; mi < MA; mi++)
#pragma unroll
        for (int ni = 0; ni < 4; ni++)
#pragma unroll
            for (int j = 0; j < 4; j++) acc[mi][ni][j] = 0.f;

    auto issue = [&](int c, int st) {
        const int seg = c / CSEG;
        const int kk  = (c % CSEG) * BK;
        const __nv_bfloat16* As = (seg == 1) ? Al : Ah;
        const __nv_bfloat16* Bs = (seg == 2) ? Bl : Bh;
#pragma unroll
        for (int r = 0; r < TM; r += RPP)
            cp16(sA + st * ATILE + (qrow + r) * TROW + qk * 16,
                 As + (size_t)(m0 + qrow + r) * Hsz + kk + qk * 8);
#pragma unroll
        for (int r = 0; r < 128; r += RPP)
            cp16(sB + st * BTILE + (qrow + r) * TROW + qk * 16,
                 Bs + (size_t)(n0 + qrow + r) * Hsz + kk + qk * 8);
        asm volatile("cp.async.commit_group;");
    };

    issue(0, 0);
    issue(1, 1);

    for (int c = 0; c < NCH; c++) {
        const int st = c % STAGES;
        if (c < NCH - 1) asm volatile("cp.async.wait_group 1;");
        else             asm volatile("cp.async.wait_group 0;");
        __syncthreads();
        if (c + 2 < NCH) issue(c + 2, (c + 2) % STAGES);

        const uint32_t bufA = sA + st * ATILE;
        const uint32_t bufB = sB + st * BTILE;
#pragma unroll
        for (int kb = 0; kb < BK; kb += 16) {
            uint32_t a[MA][4];
#pragma unroll
            for (int mi = 0; mi < MA; mi++) {
                uint32_t addr = bufA + (wm0 + mi * 16 + (lane & 15)) * TROW
                              + (kb + ((lane >> 4) << 3)) * 2;
                ldsm4(a[mi][0], a[mi][1], a[mi][2], a[mi][3], addr);
            }
            uint32_t b[4][2];
#pragma unroll
            for (int nb = 0; nb < 2; nb++) {
                uint32_t addr = bufB
                              + (wn0 + nb * 16 + (lane & 7) + ((lane >> 4) << 3)) * TROW
                              + (kb + ((lane >> 3) & 1) * 8) * 2;
                uint32_t r0, r1, r2, r3;
                ldsm4(r0, r1, r2, r3, addr);
                b[nb * 2][0] = r0;     b[nb * 2][1] = r1;
                b[nb * 2 + 1][0] = r2; b[nb * 2 + 1][1] = r3;
            }
#pragma unroll
            for (int mi = 0; mi < MA; mi++)
#pragma unroll
                for (int ni = 0; ni < 4; ni++)
                    mma16816(acc[mi][ni], a[mi], b[ni]);
        }
    }

#pragma unroll
    for (int mi = 0; mi < MA; mi++) {
#pragma unroll
        for (int ni = 0; ni < 4; ni++) {
            int r   = m0 + wm0 + mi * 16 + (lane >> 2);
            int cix = n0 + wn0 + ni * 8 + (lane & 3) * 2;
            float b0 = bias[cix], b1 = bias[cix + 1];
            *(float2*)&C[(size_t)r * ldc + cix] =
                make_float2(acc[mi][ni][0] + b0, acc[mi][ni][1] + b1);
            *(float2*)&C[(size_t)(r + 8) * ldc + cix] =
                make_float2(acc[mi][ni][2] + b0, acc[mi][ni][3] + b1);
        }
    }
}

#define SMEM_GI  (STAGES * ((128 + 128) * 144))    // 110592 (TM=128, BK=64)
#define SMEM64K  (STAGES * ((64 + 128) * 144))     // 82944  (TM=64,  BK=64)

// ---------------- GEMM wrappers --------------------------------------------
__global__ void __launch_bounds__(256, 2)
k_gi1_tc(const float* __restrict__ bih1)
{
    gemm_mma<128, 64>(g_Axh, g_Axl, blockIdx.y * 128,
                      g_Wih1h, g_Wih1l, blockIdx.x * 128,
                      bih1, g_GI1, H3);
}

// stream-1 GEMM: GH1(next) = H1(plane pp) @ Whh1^T + bhh1 ; grid (12, 8)
__global__ void __launch_bounds__(256, 2)
k_gh1_step(int pp, const float* __restrict__ bhh1)
{
    gemm_mma<64, 64>(g_H1h + (size_t)pp * Bsz * Hsz, g_H1l + (size_t)pp * Bsz * Hsz,
                     blockIdx.y * 64,
                     g_Whh1h, g_Whh1l, blockIdx.x * 128,
                     bhh1, g_GH1, H3);
}

// stream-2 GEMM: z=0: GI2 = H1(pp) @ Wih2^T ; z=1: GH2 = H2 @ Whh2^T ; grid (12,8,2)
__global__ void __launch_bounds__(256, 2)
k_gemm2_tc(int pp, const float* __restrict__ bih2, const float* __restrict__ bhh2)
{
    if (blockIdx.z == 0) {
        gemm_mma<64, 64>(g_H1h + (size_t)pp * Bsz * Hsz, g_H1l + (size_t)pp * Bsz * Hsz,
                         blockIdx.y * 64,
                         g_Wih2h, g_Wih2l, blockIdx.x * 128, bih2, g_GI2, H3);
    } else {
        gemm_mma<64, 64>(g_H2h, g_H2l, blockIdx.y * 64,
                         g_Whh2h, g_Whh2l, blockIdx.x * 128, bhh2, g_GH2, H3);
    }
}

// ---------------- elementwise ----------------------------------------------
// layer-1 gates for step t: reads GI1(t), GH1; writes H1 fp32 + plane[t&1]
__global__ void k_gates1(int t)
{
    int b = blockIdx.x, j = threadIdx.x;
    const float* gi = g_GI1 + ((size_t)t * Bsz + b) * H3;
    const float* gh = g_GH1 + (size_t)b * H3;
    float r = sigmoidf_(gi[j]           + gh[j]);
    float z = sigmoidf_(gi[Hsz + j]     + gh[Hsz + j]);
    float n = tanhf   (gi[2 * Hsz + j] + r * gh[2 * Hsz + j]);
    size_t hi = (size_t)b * Hsz + j;
    float h = g_H1[hi];
    float hnew = (1.f - z) * n + z * h;
    g_H1[hi] = hnew;
    size_t off = (size_t)(t & 1) * Bsz * Hsz;
    split_store(hnew, g_H1h + off, g_H1l + off, hi);
}

// layer-2 gates + fc output for step t
__global__ void k_gates2(int t, const float* __restrict__ Wfc,
                         const float* __restrict__ bfc, float* __restrict__ out)
{
    __shared__ float red[16];
    int b = blockIdx.x, j = threadIdx.x;
    int lane = j & 31, wid = j >> 5;
    size_t hi = (size_t)b * Hsz + j;

    const float* gi = g_GI2 + (size_t)b * H3;
    const float* gh = g_GH2 + (size_t)b * H3;
    float r = sigmoidf_(gi[j]           + gh[j]);
    float z = sigmoidf_(gi[Hsz + j]     + gh[Hsz + j]);
    float n = tanhf   (gi[2 * Hsz + j] + r * gh[2 * Hsz + j]);
    float h = g_H2[hi];
    float hnew = (1.f - z) * n + z * h;
    g_H2[hi] = hnew;
    split_store(hnew, g_H2h, g_H2l, hi);

    float v = hnew * Wfc[j];
#pragma unroll
    for (int s = 16; s > 0; s >>= 1) v += __shfl_down_sync(0xffffffffu, v, s);
    if (lane == 0) red[wid] = v;
    __syncthreads();
    if (wid == 0) {
        float vv = (lane < 16) ? red[lane] : 0.f;
#pragma unroll
        for (int s = 8; s > 0; s >>= 1) vv += __shfl_down_sync(0xffffffffu, vv, s);
        if (lane == 0) out[(size_t)b * Lsz + t] = vv + bfc[0];
    }
}

// ---------------- conversions ----------------------------------------------
__global__ void k_split_w(const float* __restrict__ Whh1, const float* __restrict__ Wih2,
                          const float* __restrict__ Whh2, const float* __restrict__ Wih1)
{
    int i = blockIdx.x * blockDim.x + threadIdx.x;
    if (i >= H3 * Hsz) return;
    split_store(Whh1[i], g_Whh1h, g_Whh1l, i);
    split_store(Wih2[i], g_Wih2h, g_Wih2l, i);
    split_store(Whh2[i], g_Whh2h, g_Whh2l, i);
    split_store(Wih1[i], g_Wih1h, g_Wih1l, i);
}

__global__ void k_convx(const float* __restrict__ x)
{
    long long i = blockIdx.x * (long long)blockDim.x + threadIdx.x;
    if (i >= (long long)Lsz * Bsz * Hsz) return;
    int k   = (int)(i & 511);
    int rem = (int)(i >> 9);
    int b   = rem & 511;
    int l   = rem >> 9;
    float v = x[(size_t)b * XW + l + k];
    split_store(v, g_Axh, g_Axl, (size_t)i);
}

__global__ void k_init(const float* __restrict__ h1in, const float* __restrict__ h2in)
{
    int i = blockIdx.x * blockDim.x + threadIdx.x;
    if (i < Bsz * Hsz) {
        float v1 = h1in[i], v2 = h2in[i];
        g_H1[i] = v1; g_H2[i] = v2;
        split_store(v1, g_H1h, g_H1l, i);   // plane 0 (prologue reads plane 0)
        split_store(v2, g_H2h, g_H2l, i);
    }
}

__global__ void k_copyout(float* __restrict__ out, int out_size)
{
    int i = blockIdx.x * blockDim.x + threadIdx.x;
    const int yN = Bsz * Lsz, hN = Bsz * Hsz;
    if (yN + 2 * hN <= out_size && i < hN) {
        out[yN + i]      = g_H1[i];
        out[yN + hN + i] = g_H2[i];
    }
}

// ---------------- launch ----------------------------------------------------
extern "C" void kernel_launch(void* const* d_in, const int* in_sizes, int n_in,
                              void* d_out, int out_size)
{
    const float* x    = (const float*)d_in[0];
    const float* h1in = (const float*)d_in[1];
    const float* h2in = (const float*)d_in[2];
    const float* Wih1 = (const float*)d_in[3];
    const float* Whh1 = (const float*)d_in[4];
    const float* bih1 = (const float*)d_in[5];
    const float* bhh1 = (const float*)d_in[6];
    const float* Wih2 = (const float*)d_in[7];
    const float* Whh2 = (const float*)d_in[8];
    const float* bih2 = (const float*)d_in[9];
    const float* bhh2 = (const float*)d_in[10];
    const float* Wfc  = (const float*)d_in[11];
    const float* bfc  = (const float*)d_in[12];
    float* out = (float*)d_out;

    // lazily-created streams/events (host-side objects only; identical work
    // is enqueued on every call)
    static cudaStream_t s1 = nullptr, s2 = nullptr;
    static cudaEvent_t e1[Lsz + 1], e2[Lsz], evF, eJ1, eJ2;
    if (s1 == nullptr) {
        cudaStreamCreateWithFlags(&s1, cudaStreamNonBlocking);
        cudaStreamCreateWithFlags(&s2, cudaStreamNonBlocking);
        for (int i = 0; i <= Lsz; i++) cudaEventCreateWithFlags(&e1[i], cudaEventDisableTiming);
        for (int i = 0; i < Lsz; i++)  cudaEventCreateWithFlags(&e2[i], cudaEventDisableTiming);
        cudaEventCreateWithFlags(&evF, cudaEventDisableTiming);
        cudaEventCreateWithFlags(&eJ1, cudaEventDisableTiming);
        cudaEventCreateWithFlags(&eJ2, cudaEventDisableTiming);
    }

    cudaFuncSetAttribute(k_gi1_tc,    cudaFuncAttributeMaxDynamicSharedMemorySize, SMEM_GI);
    cudaFuncSetAttribute(k_gh1_step,  cudaFuncAttributeMaxDynamicSharedMemorySize, SMEM64K);
    cudaFuncSetAttribute(k_gemm2_tc,  cudaFuncAttributeMaxDynamicSharedMemorySize, SMEM64K);

    // ---- prologue on default stream
    k_init<<<(Bsz * Hsz + 255) / 256, 256>>>(h1in, h2in);
    k_split_w<<<(H3 * Hsz + 255) / 256, 256>>>(Whh1, Wih2, Whh2, Wih1);
    k_convx<<<(int)(((long long)Lsz * Bsz * Hsz + 255) / 256), 256>>>(x);

    k_gi1_tc<<<dim3(H3 / 128, (Lsz * Bsz) / 128), 256, SMEM_GI>>>(bih1);

    k_gh1_step<<<dim3(12, 8), 256, SMEM64K>>>(0, bhh1);   // GH1 for t=0 from plane 0
    k_gates1<<<Bsz, Hsz>>>(0);                            // h1(0) -> plane 0

    // ---- fork
    cudaEventRecord(evF, 0);
    cudaStreamWaitEvent(s1, evF, 0);
    cudaStreamWaitEvent(s2, evF, 0);

    for (int t = 0; t < Lsz; t++) {
        // stream 1: layer-1 recurrence (iterations t=0..62 produce h1(t+1))
        if (t < Lsz - 1) {
            k_gh1_step<<<dim3(12, 8), 256, SMEM64K, s1>>>(t & 1, bhh1);
            if (t >= 1) cudaStreamWaitEvent(s1, e2[t - 1], 0);   // GI2(t-1) done reading plane[(t+1)&1]
            k_gates1<<<Bsz, Hsz, 0, s1>>>(t + 1);
            cudaEventRecord(e1[t + 1], s1);
        }
        // stream 2: layer-2 chain + output
        if (t >= 1) cudaStreamWaitEvent(s2, e1[t], 0);           // h1(t) plane ready
        k_gemm2_tc<<<dim3(12, 8, 2), 256, SMEM64K, s2>>>(t & 1, bih2, bhh2);
        cudaEventRecord(e2[t], s2);
        k_gates2<<<Bsz, Hsz, 0, s2>>>(t, Wfc, bfc, out);
    }

    // ---- join
    cudaEventRecord(eJ1, s1);
    cudaEventRecord(eJ2, s2);
    cudaStreamWaitEvent(0, eJ1, 0);
    cudaStreamWaitEvent(0, eJ2, 0);
    k_copyout<<<(Bsz * Hsz + 255) / 256, 256>>>(out, out_size);
}